// round 17
// baseline (speedup 1.0000x reference)
#include <cuda_runtime.h>

// Truncated path signature, D=6, depth K=4, L=65536 points (65535 increments).
// Output: [S1(6), S2(36), S3(216), S4(1296)] = 1554 floats.
//
// TWO kernels (R16 showed per-launch gaps are ~5-8us, so launch count is the
// tax; R14/R15 showed merge code fused into stageA spills the hot loop):
//   stageA: 148 blocks x 576 threads; 16 chunks x 28 steps (36 threads/chunk,
//           thread owns prefix ab), then 36-thread ChenRegs in-block tree fold
//           (this pairing holds 96 regs) -> g_sigA[148].
//   merge:  10 blocks x 576 threads; each element-parallel ping-pong folds 16
//           sigs (zero-pad; zero sig = Chen identity): 148 -> 10 (g_sigB);
//           the LAST block to finish (monotone atomic counter, exact-once per
//           graph replay via modulo) folds 10 -> 1 and writes d_out.

#define DD 6
#define NINC 65535
#define CPB 16
#define SPC 28                       // 148*16*28 = 66304 >= 65535, zero-padded
#define BLOCKS_A 148
#define THREADS_A (CPB * 36)         // 576
#define SIG 1554
#define O2 6
#define O3 42
#define O4 258
#define G1 16
#define B1CNT ((BLOCKS_A + G1 - 1) / G1)   // 10
#define MSLOTS 24                    // merge smem: bufA 16 sigs + bufB 8 sigs

__device__ float g_sigA[BLOCKS_A * SIG];
__device__ float g_sigB[B1CNT * SIG];
__device__ unsigned int g_fin;       // zero-init; monotone across replays

// ===========================================================================
// 36-thread ownership Chen fold (used ONLY inside stageA; holds 96 regs there)
//   C_k = A_k + B_k + sum_{i=1}^{k-1} A_i (x) B_{k-i}   (A = left/earlier)
// ===========================================================================
struct ChenRegs { float c1, c2, c3[6], c4[36]; };

__device__ __forceinline__ void chen_compute(
    const float* __restrict__ A, const float* __restrict__ B,
    int t, int a, int b, ChenRegs& r)
{
    float A1a  = A[a];
    float A2ab = A[O2 + t];
    float A3l[6], B1l[6];
#pragma unroll
    for (int c = 0; c < 6; c++) A3l[c] = A[O3 + t * 6 + c];
#pragma unroll
    for (int d = 0; d < 6; d++) B1l[d] = B[d];

    r.c1 = A1a + B[a];
    r.c2 = fmaf(A1a, B1l[b], A2ab + B[O2 + t]);

#pragma unroll
    for (int c = 0; c < 6; c++) {
        float v = A3l[c] + B[O3 + t * 6 + c];
        v = fmaf(A1a,  B[O2 + b * 6 + c], v);   // A1 (x) B2
        v = fmaf(A2ab, B1l[c],            v);   // A2 (x) B1
        r.c3[c] = v;
    }
#pragma unroll
    for (int k = 0; k < 36; k++) {              // k = c*6 + d
        float v = A[O4 + t * 36 + k] + B[O4 + t * 36 + k];
        v = fmaf(A2ab,        B[O2 + k],          v);   // A2 (x) B2
        v = fmaf(A1a,         B[O3 + b * 36 + k], v);   // A1 (x) B3
        v = fmaf(A3l[k / 6],  B1l[k % 6],         v);   // A3 (x) B1
        r.c4[k] = v;
    }
}

__device__ __forceinline__ void chen_write(
    float* __restrict__ A, int t, int a, int b, const ChenRegs& r)
{
    if (b == 0) A[a] = r.c1;
    A[O2 + t] = r.c2;
#pragma unroll
    for (int c = 0; c < 6; c++) A[O3 + t * 6 + c] = r.c3[c];
#pragma unroll
    for (int k = 0; k < 36; k++) A[O4 + t * 36 + k] = r.c4[k];
}

// Order-preserving in-place tree fold over 16 sig slots in shared memory.
__device__ __forceinline__ void tree_fold16(float* sh, int g, int t, int a, int b)
{
#pragma unroll
    for (int s = 1; s < CPB; s *= 2) {
        int i = g * 2 * s;
        bool act = (i + s) < CPB;
        ChenRegs r;
        if (act) chen_compute(sh + i * SIG, sh + (i + s) * SIG, t, a, b, r);
        __syncthreads();
        if (act) chen_write(sh + i * SIG, t, a, b, r);
        __syncthreads();
    }
}

// ===========================================================================
// Stage A (identical to R16's proven 16.2us / 96-reg version)
// ===========================================================================
__global__ __launch_bounds__(THREADS_A, 1) void stageA_kernel(const float* __restrict__ x)
{
    // Dynamic smem reused: increments (CPB*SPC*8 = 3584 floats), then
    // 16 chunk sigs (24864 floats = 99456 B).
    extern __shared__ __align__(16) float sh[];

    const int tid = threadIdx.x;
    const int g36 = tid / 36;             // chunk 0..15
    const int ab  = tid - g36 * 36;
    const int a   = ab / 6;
    const int b   = ab - a * 6;

    const long blkIncBase = (long)blockIdx.x * (CPB * SPC);
    for (int idx = tid; idx < CPB * SPC * DD; idx += THREADS_A) {
        int s = idx / DD;
        int j = idx - s * DD;
        long gidx = blkIncBase + s;
        float v = 0.0f;
        if (gidx < (long)NINC)
            v = x[(gidx + 1) * DD + j] - x[gidx * DD + j];
        sh[s * 8 + j] = v;
    }
    __syncthreads();

    float s1 = 0.0f, s2 = 0.0f;
    float s3[6], s4[36];
#pragma unroll
    for (int c = 0; c < 6; c++) s3[c] = 0.0f;
#pragma unroll
    for (int k = 0; k < 36; k++) s4[k] = 0.0f;

    const float* base = &sh[g36 * SPC * 8];
    const float THIRD = 1.0f / 3.0f;

#pragma unroll 1
    for (int t = 0; t < SPC; t++) {
        const float* p = base + t * 8;
        const float4* q = (const float4*)p;
        float4 f0 = q[0], f1 = q[1];
        float vv[6] = { f0.x, f0.y, f0.z, f0.w, f1.x, f1.y };

        float vA = p[a], vB = p[b];
        float tA = vA * THIRD, tB = vB * THIRD;

        // Horner chains (all reads of s1,s2,s3 are pre-update values)
        float V1 = fmaf(vA, 0.25f, s1);
        float V2 = fmaf(V1, tB, s2);
        float W1 = s1 + tA;
        float W2 = fmaf(W1, 0.5f * vB, s2);
        float U1 = fmaf(vA, 0.5f, s1);
        s2 = fmaf(U1, vB, s2);
        s1 += vA;
        float V2h = 0.5f * V2;

#pragma unroll
        for (int c = 0; c < 6; c++) {
            float V3 = fmaf(V2h, vv[c], s3[c]);    // uses old s3
            s3[c]    = fmaf(W2,  vv[c], s3[c]);
#pragma unroll
            for (int d = 0; d < 6; d++)
                s4[c * 6 + d] = fmaf(V3, vv[d], s4[c * 6 + d]);
        }
    }

    __syncthreads();      // increments dead; buffer becomes 16 sig slots
    {
        float* o = sh + g36 * SIG;
        if (b == 0) o[a] = s1;
        o[O2 + ab] = s2;
#pragma unroll
        for (int c = 0; c < 6; c++) o[O3 + ab * 6 + c] = s3[c];
#pragma unroll
        for (int k = 0; k < 36; k++) o[O4 + ab * 36 + k] = s4[k];
    }
    __syncthreads();

    tree_fold16(sh, g36, ab, a, b);

    for (int k = tid; k < SIG; k += THREADS_A)
        g_sigA[(long)blockIdx.x * SIG + k] = sh[k];
}

// ===========================================================================
// Element-parallel Chen merge (separate kernel; reg pressure harmless here)
// ===========================================================================
__device__ __forceinline__ float chen_elem(
    const float* __restrict__ A, const float* __restrict__ B, int e)
{
    float r = A[e] + B[e];
    if (e >= O4) {                    // level 4: m = a*216 + b*36 + c*6 + d
        int m = e - O4;
        r = fmaf(A[m / 216],     B[O3 + m % 216], r);   // A1 (x) B3
        r = fmaf(A[O2 + m / 36], B[O2 + m % 36],  r);   // A2 (x) B2
        r = fmaf(A[O3 + m / 6],  B[m % 6],        r);   // A3 (x) B1
    } else if (e >= O3) {             // level 3: m = a*36 + b*6 + c
        int m = e - O3;
        r = fmaf(A[m / 36],      B[O2 + m % 36],  r);   // A1 (x) B2
        r = fmaf(A[O2 + m / 6],  B[m % 6],        r);   // A2 (x) B1
    } else if (e >= O2) {             // level 2: m = a*6 + b
        int m = e - O2;
        r = fmaf(A[m / 6],       B[m % 6],        r);   // A1 (x) B1
    }
    return r;
}

// One ping-pong level: 576/TPM merges; merge g reads src slots 2g,2g+1,
// writes dst slot g. No aliasing -> single barrier, no staging.
template<int TPM>
__device__ __forceinline__ void chen_level_pp(
    const float* __restrict__ src, float* __restrict__ dst, int tid)
{
    const int g  = tid / TPM;
    const int lr = tid - g * TPM;
    const float* A = src + (2 * g) * SIG;
    const float* B = A + SIG;
    float* C = dst + g * SIG;
    for (int e = lr; e < SIG; e += TPM)
        C[e] = chen_elem(A, B, e);
    __syncthreads();
}

__device__ __forceinline__ void fold16_pp(float* bufA, float* bufB, int tid)
{
    chen_level_pp<72> (bufA, bufB, tid);   // 16 -> 8
    chen_level_pp<144>(bufB, bufA, tid);   //  8 -> 4
    chen_level_pp<288>(bufA, bufB, tid);   //  4 -> 2
    chen_level_pp<576>(bufB, bufA, tid);   //  2 -> 1  (result in bufA[0..SIG))
}

__global__ __launch_bounds__(THREADS_A) void merge_kernel(float* __restrict__ out)
{
    extern __shared__ __align__(16) float shm[];
    float* bufA = shm;
    float* bufB = shm + G1 * SIG;
    __shared__ unsigned int s_last;
    const int tid = threadIdx.x;

    // ---- fold my group of 16: 148 -> 10 ---------------------------------
    const int base = blockIdx.x * G1;
    int cnt = BLOCKS_A - base;
    if (cnt > G1) cnt = G1;

    for (int k = tid; k < cnt * SIG; k += THREADS_A)
        bufA[k] = g_sigA[(long)base * SIG + k];
    for (int k = cnt * SIG + tid; k < G1 * SIG; k += THREADS_A)
        bufA[k] = 0.0f;                       // identity padding
    __syncthreads();

    fold16_pp(bufA, bufB, tid);

    for (int k = tid; k < SIG; k += THREADS_A)
        g_sigB[(long)blockIdx.x * SIG + k] = bufA[k];

    // ---- last finisher folds 10 -> 1 -------------------------------------
    __syncthreads();
    if (tid == 0) {
        __threadfence();                                  // release g_sigB
        unsigned int old = atomicAdd(&g_fin, 1u);
        s_last = (((old + 1u) % (unsigned)B1CNT) == 0u) ? 1u : 0u;
    }
    __syncthreads();
    if (!s_last) return;

    __threadfence();                                      // acquire
    for (int k = tid; k < B1CNT * SIG; k += THREADS_A)
        bufA[k] = __ldcg(&g_sigB[k]);
    for (int k = B1CNT * SIG + tid; k < G1 * SIG; k += THREADS_A)
        bufA[k] = 0.0f;                       // identity padding
    __syncthreads();

    fold16_pp(bufA, bufB, tid);

    for (int k = tid; k < SIG; k += THREADS_A)
        out[k] = bufA[k];
}

// ---------------------------------------------------------------------------
extern "C" void kernel_launch(void* const* d_in, const int* in_sizes, int n_in,
                              void* d_out, int out_size)
{
    const float* x = (const float*)d_in[0];
    float* out = (float*)d_out;
    (void)in_sizes; (void)n_in; (void)out_size;

    const int smemA = G1 * SIG * (int)sizeof(float);      // 99456 B
    const int smemM = MSLOTS * SIG * (int)sizeof(float);  // 149184 B
    static int attr_done = 0;
    if (!attr_done) {
        cudaFuncSetAttribute(stageA_kernel,
                             cudaFuncAttributeMaxDynamicSharedMemorySize, smemA);
        cudaFuncSetAttribute(merge_kernel,
                             cudaFuncAttributeMaxDynamicSharedMemorySize, smemM);
        attr_done = 1;
    }

    stageA_kernel<<<BLOCKS_A, THREADS_A, smemA>>>(x);
    merge_kernel<<<B1CNT, THREADS_A, smemM>>>(out);
}